// round 5
// baseline (speedup 1.0000x reference)
#include <cuda_runtime.h>
#include <cstdint>
#include <cstddef>

// Problem constants
#define LP   197
#define BT   128
#define DIM  768
#define CA   192
#define TT   8
#define ROWS 64          // rows per CTA (two CTAs per position l)

// SMEM layout (floats)
#define GP    196              // Gs: 64 x 196 (h/gelu tile), odd-granule rows
#define GS_F  (ROWS * GP)      // 12544
#define AP1   20               // GEMM1 A stage: 64 x 20 (k-chunk 16)
#define B1P   200              // GEMM1 w1 stage: 16 x 200
#define A1_F  (ROWS * AP1)     // 1280
#define BUF_F (A1_F + 16 * B1P)// 4480 per ping-pong buffer (both live inside Gs)
#define W2P   72               // GEMM2 w2 stage: 64 x 72 (one k-stage)
#define WST_F (64 * W2P)       // 4608

#define SMEM_FLOATS (GS_F + WST_F)     // 17152
#define SMEM_BYTES  (SMEM_FLOATS * 4)  // 68608 -> 3 CTAs/SM

__device__ __forceinline__ void cp16(uint32_t saddr, const void* gptr) {
    asm volatile("cp.async.cg.shared.global [%0], [%1], 16;\n"
                 :: "r"(saddr), "l"(gptr));
}
__device__ __forceinline__ void cp_commit() { asm volatile("cp.async.commit_group;\n"); }
__device__ __forceinline__ void cp_wait0()  { asm volatile("cp.async.wait_group 0;\n"); }

__device__ __forceinline__ void ldsm_x4(uint32_t a[4], uint32_t saddr) {
    asm volatile("ldmatrix.sync.aligned.m8n8.x4.shared.b16 {%0,%1,%2,%3}, [%4];\n"
                 : "=r"(a[0]), "=r"(a[1]), "=r"(a[2]), "=r"(a[3]) : "r"(saddr));
}

__device__ __forceinline__ void mma_tf32(float c[4], const uint32_t a[4], const uint32_t b[2]) {
    asm volatile(
        "mma.sync.aligned.m16n8k8.row.col.f32.tf32.tf32.f32 "
        "{%0,%1,%2,%3}, {%4,%5,%6,%7}, {%8,%9}, {%0,%1,%2,%3};\n"
        : "+f"(c[0]), "+f"(c[1]), "+f"(c[2]), "+f"(c[3])
        : "r"(a[0]), "r"(a[1]), "r"(a[2]), "r"(a[3]),
          "r"(b[0]), "r"(b[1]));
}

__device__ __forceinline__ float gelu_exact(float v) {
    return 0.5f * v * (1.0f + erff(v * 0.70710678118654752f));
}

__global__ void __launch_bounds__(256, 3)
fused_adapter_kernel(const float* __restrict__ x,
                     const float* __restrict__ w1,
                     const float* __restrict__ b1,
                     const float* __restrict__ cw,   // (CA,3)
                     const float* __restrict__ cb,   // (CA,)
                     const float* __restrict__ w2,
                     const float* __restrict__ b2,
                     float* __restrict__ out)
{
    extern __shared__ float smem[];
    float* Gs = smem;                 // 64 x GP (GEMM1 ping-pong buffers alias here)
    float* Wr = smem + GS_F;          // GEMM2 w2 k-stage

    const uint32_t smem_u = (uint32_t)__cvta_generic_to_shared(smem);

    const int tid  = threadIdx.x;
    const int wid  = tid >> 5;
    const int lane = tid & 31;
    const int gid  = lane >> 2;   // 0..7
    const int ctig = lane & 3;    // 0..3

    const int l    = blockIdx.x >> 1;
    const int half = blockIdx.x & 1;
    const int lsrc = (l == 0) ? 1 : l;

    const int wm  = wid & 1;
    const int wn1 = wid >> 1;

    // ldmatrix per-lane offsets (words)
    const int a1_lane_off = (lane & 15) * AP1 + ((lane >> 4) << 2);
    const int g_lane_off  = (lane & 15) * GP  + ((lane >> 4) << 2);

    const float* xA = x + ((size_t)lsrc * BT + half * ROWS) * DIM;

    // staging coords (GEMM1): A: 1 cp16/thread, B1: 3 cp16/thread
    const int a_row = tid >> 2;
    const int a_c4  = (tid & 3) << 2;

    // ================= GEMM1: k-chunk 16, cp.async ping-pong inside Gs ==========
    float acc[2][6][4];
    #pragma unroll
    for (int i = 0; i < 2; i++)
        #pragma unroll
        for (int j = 0; j < 6; j++)
            #pragma unroll
            for (int k = 0; k < 4; k++) acc[i][j][k] = 0.0f;

    // prologue: stage chunk 0 into buffer 0
    {
        cp16(smem_u + (a_row * AP1 + a_c4) * 4, xA + (size_t)a_row * DIM + a_c4);
        #pragma unroll
        for (int i = 0; i < 3; i++) {
            int idx = tid + (i << 8);
            int row = idx / 48;
            int c4  = (idx % 48) << 2;
            cp16(smem_u + (A1_F + row * B1P + c4) * 4, w1 + (size_t)row * CA + c4);
        }
        cp_commit();
        cp_wait0();
    }
    __syncthreads();

    #pragma unroll 1
    for (int ic = 0; ic < 48; ic++) {
        const int cur = (ic & 1) * BUF_F;
        if (ic < 47) {
            const int kc = (ic + 1) << 4;
            const uint32_t nb = smem_u + (((ic + 1) & 1) * BUF_F) * 4;
            cp16(nb + (a_row * AP1 + a_c4) * 4, xA + (size_t)a_row * DIM + kc + a_c4);
            #pragma unroll
            for (int i = 0; i < 3; i++) {
                int idx = tid + (i << 8);
                int row = idx / 48;
                int c4  = (idx % 48) << 2;
                cp16(nb + (A1_F + row * B1P + c4) * 4,
                     w1 + (size_t)(kc + row) * CA + c4);
            }
            cp_commit();
        }

        const uint32_t As_u = smem_u + cur * 4;
        const float*   B1_  = smem + cur + A1_F;

        #pragma unroll
        for (int ks = 0; ks < 2; ks++) {
            int k0 = ks << 3;
            uint32_t a0[4], a1[4];
            ldsm_x4(a0, As_u + ((wm * 32 +  0) * AP1 + k0 + a1_lane_off) * 4);
            ldsm_x4(a1, As_u + ((wm * 32 + 16) * AP1 + k0 + a1_lane_off) * 4);
            #pragma unroll
            for (int nt = 0; nt < 6; nt++) {
                uint32_t b[2];
                int n0 = wn1 * 48 + nt * 8 + gid;
                b[0] = __float_as_uint(B1_[(k0 + ctig) * B1P + n0]);
                b[1] = __float_as_uint(B1_[(k0 + ctig + 4) * B1P + n0]);
                mma_tf32(acc[0][nt], a0, b);
                mma_tf32(acc[1][nt], a1, b);
            }
        }
        if (ic < 47) cp_wait0();
        __syncthreads();
    }

    // store h + b1 into Gs (overwrites staging buffers; all MMAs done)
    #pragma unroll
    for (int mt = 0; mt < 2; mt++) {
        #pragma unroll
        for (int nt = 0; nt < 6; nt++) {
            int r0 = wm * 32 + mt * 16 + gid;
            int c0 = wn1 * 48 + nt * 8 + 2 * ctig;
            float bb0 = b1[c0], bb1 = b1[c0 + 1];
            Gs[r0 * GP + c0]           = acc[mt][nt][0] + bb0;
            Gs[r0 * GP + c0 + 1]       = acc[mt][nt][1] + bb1;
            Gs[(r0 + 8) * GP + c0]     = acc[mt][nt][2] + bb0;
            Gs[(r0 + 8) * GP + c0 + 1] = acc[mt][nt][3] + bb1;
        }
    }

    // prefetch GEMM2 stage (nc=0, kst=0): w2 rows 0..63, cols 0..63
    float4 w2reg[4];
    {
        #pragma unroll
        for (int i = 0; i < 4; i++) {
            int idx = tid + (i << 8);
            int row = idx >> 4;
            int c4  = (idx & 15) << 2;
            w2reg[i] = *(const float4*)(w2 + (size_t)row * DIM + c4);
        }
    }

    __syncthreads();

    // ============ Temporal mixing fused with GELU (l >= 1), else GELU only ======
    if (l > 0) {
        #pragma unroll 1
        for (int i = 0; i < 6; i++) {
            int task = tid + (i << 8);
            int b = task / CA;
            int c = task % CA;
            float cw0 = cw[c * 3 + 0];
            float cw1 = cw[c * 3 + 1];
            float cw2 = cw[c * 3 + 2];
            float cbc = cb[c];
            float hv[TT];
            float S = 0.0f;
            #pragma unroll
            for (int t = 0; t < TT; t++) {
                hv[t] = Gs[(b * TT + t) * GP + c];
                float w = cw1 * (float)t - (float)(TT - 1 - t);
                if (t < TT - 1) w += cw0 * (float)(t + 1);
                if (t >= 1)     w += cw2 * (float)(t - 1);
                S += w * hv[t];
            }
            float r = S * (1.0f / 28.0f) + cbc;
            #pragma unroll
            for (int t = 0; t < TT; t++)
                Gs[(b * TT + t) * GP + c] = gelu_exact(hv[t] + r);
        }
    } else {
        #pragma unroll 4
        for (int i = 0; i < 48; i++) {
            int idx = tid + (i << 8);
            int r = idx / CA;
            int c = idx % CA;
            Gs[r * GP + c] = gelu_exact(Gs[r * GP + c]);
        }
    }
    __syncthreads();

    // ===== GEMM2: n-chunks of 64, each in 3 k-stages of 64; reg prefetch ========
    const float* xR   = x   + ((size_t)l * BT + half * ROWS) * DIM;
    float*       outR = out + ((size_t)l * BT + half * ROWS) * DIM;

    const int wn2 = wid >> 1;   // 0..3
    const int st_row = tid >> 4;          // 0..15 (x16 over i)
    const int st_c4  = (tid & 15) << 2;

    #pragma unroll 1
    for (int nc = 0; nc < 12; nc++) {
        const int nbase = nc * 64;

        float acc2[2][2][4];
        #pragma unroll
        for (int i = 0; i < 2; i++)
            #pragma unroll
            for (int j = 0; j < 2; j++)
                #pragma unroll
                for (int k = 0; k < 4; k++) acc2[i][j][k] = 0.0f;

        float2 xres[2][2][2];
        float2 bb[2];

        #pragma unroll 1
        for (int kst = 0; kst < 3; kst++) {
            // commit prefetched w2 stage to smem
            #pragma unroll
            for (int i = 0; i < 4; i++) {
                int row = st_row + (i << 4);
                *(float4*)(Wr + row * W2P + st_c4) = w2reg[i];
            }
            __syncthreads();

            // prefetch next stage (overlaps MMA)
            int s = nc * 3 + kst;
            if (s < 35) {
                int nc2  = (s + 1) / 3;
                int kst2 = (s + 1) % 3;
                const float* gsrc = w2 + (size_t)(kst2 * 64) * DIM + nc2 * 64;
                #pragma unroll
                for (int i = 0; i < 4; i++) {
                    int row = st_row + (i << 4);
                    w2reg[i] = *(const float4*)(gsrc + (size_t)row * DIM + st_c4);
                }
            }
            // prefetch residual + bias during last k-stage
            if (kst == 2) {
                #pragma unroll
                for (int nt = 0; nt < 2; nt++) {
                    int c0g = nbase + wn2 * 16 + nt * 8 + 2 * ctig;
                    bb[nt] = *(const float2*)(b2 + c0g);
                    #pragma unroll
                    for (int mt = 0; mt < 2; mt++) {
                        int r0 = wm * 32 + mt * 16 + gid;
                        size_t o0 = (size_t)r0 * DIM + c0g;
                        xres[mt][nt][0] = *(const float2*)(xR + o0);
                        xres[mt][nt][1] = *(const float2*)(xR + o0 + (size_t)8 * DIM);
                    }
                }
            }

            #pragma unroll
            for (int ks = 0; ks < 8; ks++) {
                int k0  = ks << 3;
                int k0g = kst * 64 + k0;
                uint32_t a0[4], a1[4];
                ldsm_x4(a0, smem_u + ((wm * 32 +  0) * GP + k0g + g_lane_off) * 4);
                ldsm_x4(a1, smem_u + ((wm * 32 + 16) * GP + k0g + g_lane_off) * 4);
                #pragma unroll
                for (int nt = 0; nt < 2; nt++) {
                    uint32_t b[2];
                    int n0 = wn2 * 16 + nt * 8 + gid;
                    b[0] = __float_as_uint(Wr[(k0 + ctig) * W2P + n0]);
                    b[1] = __float_as_uint(Wr[(k0 + ctig + 4) * W2P + n0]);
                    mma_tf32(acc2[0][nt], a0, b);
                    mma_tf32(acc2[1][nt], a1, b);
                }
            }
            __syncthreads();
        }

        // epilogue from registers
        #pragma unroll
        for (int mt = 0; mt < 2; mt++) {
            #pragma unroll
            for (int nt = 0; nt < 2; nt++) {
                int r0  = wm * 32 + mt * 16 + gid;
                int c0g = nbase + wn2 * 16 + nt * 8 + 2 * ctig;
                size_t o0 = (size_t)r0 * DIM + c0g;
                float2 ov0;
                ov0.x = xres[mt][nt][0].x + acc2[mt][nt][0] + bb[nt].x;
                ov0.y = xres[mt][nt][0].y + acc2[mt][nt][1] + bb[nt].y;
                *(float2*)(outR + o0) = ov0;
                float2 ov1;
                ov1.x = xres[mt][nt][1].x + acc2[mt][nt][2] + bb[nt].x;
                ov1.y = xres[mt][nt][1].y + acc2[mt][nt][3] + bb[nt].y;
                *(float2*)(outR + o0 + (size_t)8 * DIM) = ov1;
            }
        }
    }
}

extern "C" void kernel_launch(void* const* d_in, const int* in_sizes, int n_in,
                              void* d_out, int out_size) {
    const float* x  = (const float*)d_in[0];
    const float* w1 = (const float*)d_in[1];
    const float* b1 = (const float*)d_in[2];
    const float* cw = (const float*)d_in[3];
    const float* cb = (const float*)d_in[4];
    const float* w2 = (const float*)d_in[5];
    const float* b2 = (const float*)d_in[6];
    float* out = (float*)d_out;

    cudaFuncSetAttribute(fused_adapter_kernel,
                         cudaFuncAttributeMaxDynamicSharedMemorySize, SMEM_BYTES);
    fused_adapter_kernel<<<LP * 2, 256, SMEM_BYTES>>>(x, w1, b1, cw, cb, w2, b2, out);
}